// round 1
// baseline (speedup 1.0000x reference)
#include <cuda_runtime.h>

#define NB 8
#define NS 2048
#define ND 1024
#define NFF 1024
#define NROWS (NB * NS)   // 16384

// ---------------- scratch (no cudaMalloc allowed) ----------------
__device__ float g_xn  [(size_t)NROWS * ND];
__device__ float g_q   [(size_t)NROWS * ND];
__device__ float g_k   [(size_t)NROWS * ND];
__device__ float g_attn[(size_t)NROWS * ND];
__device__ float g_x2  [(size_t)NROWS * ND];
__device__ float g_xn2 [(size_t)NROWS * ND];
__device__ float g_h   [(size_t)NROWS * NFF];

// ---------------- LayerNorm: one block (256 thr) per row of 1024 ----------------
__global__ void __launch_bounds__(256) ln_kernel(const float* __restrict__ x,
                                                 const float* __restrict__ g,
                                                 const float* __restrict__ b,
                                                 float* __restrict__ out)
{
    size_t row = blockIdx.x;
    const float4* xr = (const float4*)(x + row * ND);
    int t = threadIdx.x;
    float4 xv = xr[t];
    float s  = xv.x + xv.y + xv.z + xv.w;
    float ss = xv.x * xv.x + xv.y * xv.y + xv.z * xv.z + xv.w * xv.w;
#pragma unroll
    for (int o = 16; o; o >>= 1) {
        s  += __shfl_xor_sync(0xffffffffu, s,  o);
        ss += __shfl_xor_sync(0xffffffffu, ss, o);
    }
    __shared__ float sh_s[8], sh_ss[8];
    if ((t & 31) == 0) { sh_s[t >> 5] = s; sh_ss[t >> 5] = ss; }
    __syncthreads();
    float ts = 0.f, tss = 0.f;
#pragma unroll
    for (int i = 0; i < 8; i++) { ts += sh_s[i]; tss += sh_ss[i]; }
    float mean = ts * (1.f / ND);
    float var  = tss * (1.f / ND) - mean * mean;
    float rstd = rsqrtf(var + 1e-5f);
    float4 gv = ((const float4*)g)[t];
    float4 bv = ((const float4*)b)[t];
    float4 ov;
    ov.x = (xv.x - mean) * rstd * gv.x + bv.x;
    ov.y = (xv.y - mean) * rstd * gv.y + bv.y;
    ov.z = (xv.z - mean) * rstd * gv.z + bv.z;
    ov.w = (xv.w - mean) * rstd * gv.w + bv.w;
    ((float4*)(out + row * ND))[t] = ov;
}

// ---------------- softmax: one block (256 thr) per row of 2048 ----------------
__global__ void __launch_bounds__(256) softmax_kernel(float* __restrict__ w)
{
    float* p = w + (size_t)blockIdx.x * NS;
    int t = threadIdx.x;
    float4 v0 = ((const float4*)p)[t];
    float4 v1 = ((const float4*)p)[t + 256];
    float mx = fmaxf(fmaxf(fmaxf(v0.x, v0.y), fmaxf(v0.z, v0.w)),
                     fmaxf(fmaxf(v1.x, v1.y), fmaxf(v1.z, v1.w)));
#pragma unroll
    for (int o = 16; o; o >>= 1) mx = fmaxf(mx, __shfl_xor_sync(0xffffffffu, mx, o));
    __shared__ float shm[8];
    __shared__ float shs[8];
    if ((t & 31) == 0) shm[t >> 5] = mx;
    __syncthreads();
    mx = shm[0];
#pragma unroll
    for (int i = 1; i < 8; i++) mx = fmaxf(mx, shm[i]);

    float e[8];
    e[0] = __expf(v0.x - mx); e[1] = __expf(v0.y - mx);
    e[2] = __expf(v0.z - mx); e[3] = __expf(v0.w - mx);
    e[4] = __expf(v1.x - mx); e[5] = __expf(v1.y - mx);
    e[6] = __expf(v1.z - mx); e[7] = __expf(v1.w - mx);
    float s = e[0] + e[1] + e[2] + e[3] + e[4] + e[5] + e[6] + e[7];
#pragma unroll
    for (int o = 16; o; o >>= 1) s += __shfl_xor_sync(0xffffffffu, s, o);
    if ((t & 31) == 0) shs[t >> 5] = s;
    __syncthreads();
    s = 0.f;
#pragma unroll
    for (int i = 0; i < 8; i++) s += shs[i];
    float inv = 1.f / s;
    ((float4*)p)[t]       = make_float4(e[0] * inv, e[1] * inv, e[2] * inv, e[3] * inv);
    ((float4*)p)[t + 256] = make_float4(e[4] * inv, e[5] * inv, e[6] * inv, e[7] * inv);
}

// ---------------- SGEMM 128x128x8, 256 threads, 8x8 microtile ----------------
// C[M,N] = alpha * A[M,K] * op(B) (+ bias[N]) (mask -> -1e9) (+ resid) (ReLU)
// TRANSB: B is [N,K] row-major (B^T applied). Batched via blockIdx.z + strides.
// Requires M,N % 128 == 0, K % 8 == 0 (all shapes here satisfy this).
template <bool TRANSB, bool RELU, bool MASKED>
__global__ void __launch_bounds__(256) gemm_kernel(
    const float* __restrict__ A, const float* __restrict__ Bm,
    float* __restrict__ C, int M, int N, int K,
    long long sA, long long sB, long long sC,
    const float* __restrict__ bias,
    const float* __restrict__ resid,
    const int* __restrict__ mask,
    float alpha)
{
    int bz = blockIdx.z;
    A  += (size_t)bz * sA;
    Bm += (size_t)bz * sB;
    C  += (size_t)bz * sC;
    const int* maskp = MASKED ? (mask + (size_t)bz * N) : nullptr;

    int m0 = blockIdx.y * 128, n0 = blockIdx.x * 128;
    __shared__ float As[8][128];
    __shared__ float Bs[8][128];
    int tid  = threadIdx.x;
    int arow = tid >> 1, acol = (tid & 1) * 4;      // 128 rows x 8 cols via float4
    int brow = tid >> 5, bcol = (tid & 31) * 4;     // 8 rows x 128 cols via float4
    int tx = tid & 15, ty = tid >> 4;

    float acc[8][8];
#pragma unroll
    for (int i = 0; i < 8; i++)
#pragma unroll
        for (int j = 0; j < 8; j++) acc[i][j] = 0.f;

    for (int k0 = 0; k0 < K; k0 += 8) {
        float4 av = *(const float4*)(A + (size_t)(m0 + arow) * K + k0 + acol);
        As[acol + 0][arow] = av.x;
        As[acol + 1][arow] = av.y;
        As[acol + 2][arow] = av.z;
        As[acol + 3][arow] = av.w;
        if (TRANSB) {
            float4 bv = *(const float4*)(Bm + (size_t)(n0 + arow) * K + k0 + acol);
            Bs[acol + 0][arow] = bv.x;
            Bs[acol + 1][arow] = bv.y;
            Bs[acol + 2][arow] = bv.z;
            Bs[acol + 3][arow] = bv.w;
        } else {
            float4 bv = *(const float4*)(Bm + (size_t)(k0 + brow) * N + n0 + bcol);
            *(float4*)&Bs[brow][bcol] = bv;
        }
        __syncthreads();
#pragma unroll
        for (int kk = 0; kk < 8; kk++) {
            float4 a0 = *(const float4*)&As[kk][ty * 8];
            float4 a1 = *(const float4*)&As[kk][ty * 8 + 4];
            float4 b0 = *(const float4*)&Bs[kk][tx * 8];
            float4 b1 = *(const float4*)&Bs[kk][tx * 8 + 4];
            float ra[8] = {a0.x, a0.y, a0.z, a0.w, a1.x, a1.y, a1.z, a1.w};
            float rb[8] = {b0.x, b0.y, b0.z, b0.w, b1.x, b1.y, b1.z, b1.w};
#pragma unroll
            for (int i = 0; i < 8; i++)
#pragma unroll
                for (int j = 0; j < 8; j++)
                    acc[i][j] += ra[i] * rb[j];
        }
        __syncthreads();
    }

    float bvs[8];
#pragma unroll
    for (int j = 0; j < 8; j++) bvs[j] = bias ? bias[n0 + tx * 8 + j] : 0.f;
    int mv[8];
    if (MASKED) {
#pragma unroll
        for (int j = 0; j < 8; j++) mv[j] = maskp[n0 + tx * 8 + j];
    }
#pragma unroll
    for (int i = 0; i < 8; i++) {
        size_t row  = (size_t)(m0 + ty * 8 + i);
        size_t base = row * N + n0 + tx * 8;
        float v[8];
#pragma unroll
        for (int j = 0; j < 8; j++) {
            float t = acc[i][j] * alpha + bvs[j];
            if (MASKED && mv[j] == 0) t = -1e9f;
            if (resid) t += resid[base + j];
            if (RELU) t = fmaxf(t, 0.f);
            v[j] = t;
        }
        *(float4*)&C[base]     = make_float4(v[0], v[1], v[2], v[3]);
        *(float4*)&C[base + 4] = make_float4(v[4], v[5], v[6], v[7]);
    }
}

// ---------------- driver ----------------
extern "C" void kernel_launch(void* const* d_in, const int* in_sizes, int n_in,
                              void* d_out, int out_size)
{
    const float* x    = (const float*)d_in[0];
    const int*   mask = (const int*)  d_in[1];
    const float* ln1g = (const float*)d_in[2];
    const float* ln1b = (const float*)d_in[3];
    const float* Wq   = (const float*)d_in[4];
    const float* bq   = (const float*)d_in[5];
    const float* Wk   = (const float*)d_in[6];
    const float* bk   = (const float*)d_in[7];
    const float* Wo   = (const float*)d_in[8];
    const float* bo   = (const float*)d_in[9];
    const float* ln2g = (const float*)d_in[10];
    const float* ln2b = (const float*)d_in[11];
    const float* W1   = (const float*)d_in[12];
    const float* b1   = (const float*)d_in[13];
    const float* W2   = (const float*)d_in[14];
    const float* b2   = (const float*)d_in[15];

    float* out  = (float*)d_out;                       // (B,S,D)
    float* wout = out + (size_t)NROWS * ND;            // (B,S,S) attention weights

    float *xn, *q, *k, *attn, *x2, *xn2, *h;
    cudaGetSymbolAddress((void**)&xn,   g_xn);
    cudaGetSymbolAddress((void**)&q,    g_q);
    cudaGetSymbolAddress((void**)&k,    g_k);
    cudaGetSymbolAddress((void**)&attn, g_attn);
    cudaGetSymbolAddress((void**)&x2,   g_x2);
    cudaGetSymbolAddress((void**)&xn2,  g_xn2);
    cudaGetSymbolAddress((void**)&h,    g_h);

    // 1) xn = LN1(x)
    ln_kernel<<<NROWS, 256>>>(x, ln1g, ln1b, xn);

    dim3 gP(ND / 128, NROWS / 128, 1);   // 16384 x 1024 projections
    // 2) q = xn @ Wq + bq ; 3) k = xn @ Wk + bk  (v == k, faithful reference bug)
    gemm_kernel<false, false, false><<<gP, 256>>>(xn, Wq, q, NROWS, ND, ND,
                                                  0, 0, 0, bq, nullptr, nullptr, 1.f);
    gemm_kernel<false, false, false><<<gP, 256>>>(xn, Wk, k, NROWS, ND, ND,
                                                  0, 0, 0, bk, nullptr, nullptr, 1.f);

    // 4) scores = (q @ k^T)/32, masked -> written into w output region
    dim3 gS(NS / 128, NS / 128, NB);
    gemm_kernel<true, false, true><<<gS, 256>>>(q, k, wout, NS, NS, ND,
                                                (long long)NS * ND, (long long)NS * ND,
                                                (long long)NS * NS,
                                                nullptr, nullptr, mask, 0.03125f);
    // 5) softmax in place (this IS the w output)
    softmax_kernel<<<NROWS, 256>>>(wout);

    // 6) attn = w @ v  (v == k), batched
    dim3 gA(ND / 128, NS / 128, NB);
    gemm_kernel<false, false, false><<<gA, 256>>>(wout, k, attn, NS, ND, NS,
                                                  (long long)NS * NS, (long long)NS * ND,
                                                  (long long)NS * ND,
                                                  nullptr, nullptr, nullptr, 1.f);

    // 7) x2 = x + attn @ Wo + bo
    gemm_kernel<false, false, false><<<gP, 256>>>(attn, Wo, x2, NROWS, ND, ND,
                                                  0, 0, 0, bo, x, nullptr, 1.f);

    // 8) xn2 = LN2(x2)
    ln_kernel<<<NROWS, 256>>>(x2, ln2g, ln2b, xn2);

    // 9) h = relu(xn2 @ W1 + b1)
    gemm_kernel<false, true, false><<<gP, 256>>>(xn2, W1, h, NROWS, NFF, ND,
                                                 0, 0, 0, b1, nullptr, nullptr, 1.f);

    // 10) out = x2 + h @ W2 + b2
    gemm_kernel<false, false, false><<<gP, 256>>>(h, W2, out, NROWS, ND, NFF,
                                                  0, 0, 0, b2, x2, nullptr, 1.f);
}

// round 3
// speedup vs baseline: 2.0849x; 2.0849x over previous
#include <cuda_runtime.h>
#include <cuda_bf16.h>
#include <stdint.h>

#define NB 8
#define NS 2048
#define ND 1024
#define NROWS (NB * NS)          // 16384
#define WSZ ((size_t)ND * ND)

// ---------------- scratch (no cudaMalloc allowed) ----------------
__device__ __nv_bfloat16 g_xn_h [(size_t)NROWS * ND], g_xn_l [(size_t)NROWS * ND];
__device__ __nv_bfloat16 g_q_h  [(size_t)NROWS * ND], g_q_l  [(size_t)NROWS * ND];
__device__ __nv_bfloat16 g_k_h  [(size_t)NROWS * ND], g_k_l  [(size_t)NROWS * ND];
__device__ __nv_bfloat16 g_kT_h [(size_t)NROWS * ND], g_kT_l [(size_t)NROWS * ND];
__device__ __nv_bfloat16 g_w_h  [(size_t)NB * NS * NS], g_w_l [(size_t)NB * NS * NS];
__device__ __nv_bfloat16 g_at_h [(size_t)NROWS * ND], g_at_l [(size_t)NROWS * ND];
__device__ float         g_x2   [(size_t)NROWS * ND];
__device__ __nv_bfloat16 g_xn2_h[(size_t)NROWS * ND], g_xn2_l[(size_t)NROWS * ND];
__device__ __nv_bfloat16 g_h_h  [(size_t)NROWS * ND], g_h_l  [(size_t)NROWS * ND];
__device__ __nv_bfloat16 g_wt   [5 * 2 * WSZ];

// ---------------- helpers ----------------
__device__ __forceinline__ uint32_t smem_u32(const void* p) {
    uint32_t a;
    asm("{ .reg .u64 t; cvta.to.shared.u64 t, %1; cvt.u32.u64 %0, t; }" : "=r"(a) : "l"(p));
    return a;
}
__device__ __forceinline__ void cp16(uint32_t dst, const void* src) {
    asm volatile("cp.async.cg.shared.global [%0], [%1], 16;" :: "r"(dst), "l"(src));
}
__device__ __forceinline__ void ldmA(uint32_t* a, uint32_t addr) {
    asm volatile("ldmatrix.sync.aligned.m8n8.x4.shared.b16 {%0,%1,%2,%3}, [%4];"
                 : "=r"(a[0]), "=r"(a[1]), "=r"(a[2]), "=r"(a[3]) : "r"(addr));
}
__device__ __forceinline__ void ldmB(uint32_t* b, uint32_t addr) {
    asm volatile("ldmatrix.sync.aligned.m8n8.x2.shared.b16 {%0,%1}, [%2];"
                 : "=r"(b[0]), "=r"(b[1]) : "r"(addr));
}
__device__ __forceinline__ void mma16816(float* c, const uint32_t* a, const uint32_t* b) {
    asm volatile("mma.sync.aligned.m16n8k16.row.col.f32.bf16.bf16.f32 "
                 "{%0,%1,%2,%3}, {%4,%5,%6,%7}, {%8,%9}, {%0,%1,%2,%3};"
                 : "+f"(c[0]), "+f"(c[1]), "+f"(c[2]), "+f"(c[3])
                 : "r"(a[0]), "r"(a[1]), "r"(a[2]), "r"(a[3]), "r"(b[0]), "r"(b[1]));
}

// smem per stage: A_h 8K | A_l 8K | B_h 8K | B_l 8K = 32KB; 2 stages = 64KB
#define STAGE 32768
#define SMEMSZ (2 * STAGE)
// tile offset inside an 8K operand block: 8x8 bf16 tiles, id = kt8*16 + rt8
__device__ __forceinline__ uint32_t toff(int rt8, int kt8) {
    return (uint32_t)((kt8 * 16 + rt8) * 128);
}

// ---------------- warp-MMA split-bf16 GEMM: 128x128 CTA tile, kchunk 32 ----------------
// D = alpha * A[M,K] * B[N,K]^T  (+bias) (mask==0 -> -1e9) (+resid) (relu)
template <bool BIAS, bool RELU, bool MASK, bool RESID, bool HILO>
__global__ void __launch_bounds__(256, 2) gemm_tc(
    const __nv_bfloat16* __restrict__ Ahi, const __nv_bfloat16* __restrict__ Alo,
    const __nv_bfloat16* __restrict__ Bhi, const __nv_bfloat16* __restrict__ Blo,
    int M, int N, int K,
    long long sA, long long sB, long long sC,
    float* __restrict__ Cf,
    __nv_bfloat16* __restrict__ Chi, __nv_bfloat16* __restrict__ Clo,
    const float* __restrict__ bias,
    const float* __restrict__ resid,
    const int* __restrict__ mask,
    float alpha)
{
    extern __shared__ char smem[];
    const int tid  = threadIdx.x;
    const int lane = tid & 31, wid = tid >> 5;
    const int wm = wid & 1, wn = wid >> 1;          // 2 x 4 warp grid
    const int bz = blockIdx.z;
    const size_t aoff = (size_t)bz * sA, boff = (size_t)bz * sB, coff = (size_t)bz * sC;
    Ahi += aoff; Alo += aoff; Bhi += boff; Blo += boff;
    if (!HILO) Cf += coff; else { Chi += coff; Clo += coff; }
    const int m0 = blockIdx.y * 128, n0 = blockIdx.x * 128;

    const uint32_t sb = smem_u32(smem);

    // per-thread staging map: idx = tid + half*256 -> row = idx>>2, kt8 = idx&3
    const int r_lo = tid >> 2, kt = tid & 3;
    const uint32_t d_lo = (uint32_t)((kt * 16 + (r_lo >> 3)) * 128 + (r_lo & 7) * 16);
    const int r_hi = r_lo + 64;
    const uint32_t d_hi = (uint32_t)((kt * 16 + (r_hi >> 3)) * 128 + (r_hi & 7) * 16);

    float acc[4][4][4];
#pragma unroll
    for (int i = 0; i < 4; i++)
#pragma unroll
        for (int j = 0; j < 4; j++)
#pragma unroll
            for (int q = 0; q < 4; q++) acc[i][j][q] = 0.f;

    const int nk = K >> 5;

    auto issue = [&](int i) {
        const uint32_t s = sb + (uint32_t)(i & 1) * STAGE;
        const int k0 = i << 5;
        const size_t ga_lo = (size_t)(m0 + r_lo) * K + k0 + kt * 8;
        const size_t ga_hi = (size_t)(m0 + r_hi) * K + k0 + kt * 8;
        const size_t gb_lo = (size_t)(n0 + r_lo) * K + k0 + kt * 8;
        const size_t gb_hi = (size_t)(n0 + r_hi) * K + k0 + kt * 8;
        cp16(s +         d_lo, Ahi + ga_lo);
        cp16(s +         d_hi, Ahi + ga_hi);
        cp16(s +  8192 + d_lo, Alo + ga_lo);
        cp16(s +  8192 + d_hi, Alo + ga_hi);
        cp16(s + 16384 + d_lo, Bhi + gb_lo);
        cp16(s + 16384 + d_hi, Bhi + gb_hi);
        cp16(s + 24576 + d_lo, Blo + gb_lo);
        cp16(s + 24576 + d_hi, Blo + gb_hi);
        asm volatile("cp.async.commit_group;");
    };

    issue(0);
    for (int i = 0; i < nk; i++) {
        if (i + 1 < nk) {
            issue(i + 1);
            asm volatile("cp.async.wait_group 1;");
        } else {
            asm volatile("cp.async.wait_group 0;");
        }
        __syncthreads();

        const uint32_t sA_h = sb + (uint32_t)(i & 1) * STAGE;
        const uint32_t sA_l = sA_h + 8192;
        const uint32_t sB_h = sA_h + 16384;
        const uint32_t sB_l = sA_h + 24576;
        const int mrow = lane & 7;            // ldmatrix source row within tile

#pragma unroll
        for (int ks = 0; ks < 2; ks++) {
            // B fragments: x2, matrices (nt8, ks*2) and (nt8, ks*2+1)
            uint32_t bh[4][2], bl[4][2];
            const int bmi = (lane >> 3) & 1;  // which k-subtile this lane addresses
#pragma unroll
            for (int nt = 0; nt < 4; nt++) {
                const int nt8 = wn * 4 + nt;
                const uint32_t off = toff(nt8, ks * 2 + bmi) + mrow * 16;
                ldmB(bh[nt], sB_h + off);
                ldmB(bl[nt], sB_l + off);
            }
#pragma unroll
            for (int mt = 0; mt < 4; mt++) {
                const int mi = lane >> 3;
                const int dm = mi & 1, dk = mi >> 1;
                const int mt8 = wm * 8 + mt * 2 + dm;
                const uint32_t off = toff(mt8, ks * 2 + dk) + mrow * 16;
                uint32_t ah[4], al[4];
                ldmA(ah, sA_h + off);
                ldmA(al, sA_l + off);
#pragma unroll
                for (int nt = 0; nt < 4; nt++) {
                    mma16816(acc[mt][nt], ah, bh[nt]);
                    mma16816(acc[mt][nt], ah, bl[nt]);
                    mma16816(acc[mt][nt], al, bh[nt]);
                }
            }
        }
        __syncthreads();
    }

    // ---------------- epilogue ----------------
    const int cq = (lane & 3) * 2, rq = lane >> 2;
#pragma unroll
    for (int nt = 0; nt < 4; nt++) {
        const int c = n0 + wn * 32 + nt * 8 + cq;
        float bv0 = 0.f, bv1 = 0.f;
        if (BIAS) { bv0 = bias[c]; bv1 = bias[c + 1]; }
        int mk0 = 1, mk1 = 1;
        if (MASK) {
            const int* mp = mask + (size_t)bz * N;
            mk0 = mp[c]; mk1 = mp[c + 1];
        }
#pragma unroll
        for (int mt = 0; mt < 4; mt++) {
            const int r0 = m0 + wm * 64 + mt * 16 + rq;
#pragma unroll
            for (int h = 0; h < 2; h++) {
                const int row = r0 + h * 8;
                float v0 = acc[mt][nt][h * 2 + 0] * alpha + bv0;
                float v1 = acc[mt][nt][h * 2 + 1] * alpha + bv1;
                if (MASK) { if (mk0 == 0) v0 = -1e9f; if (mk1 == 0) v1 = -1e9f; }
                if (RESID) {
                    float2 rv = *(const float2*)(resid + (size_t)row * N + c);
                    v0 += rv.x; v1 += rv.y;
                }
                if (RELU) { v0 = fmaxf(v0, 0.f); v1 = fmaxf(v1, 0.f); }
                if (HILO) {
                    __nv_bfloat16 h0 = __float2bfloat16(v0);
                    __nv_bfloat16 h1 = __float2bfloat16(v1);
                    *(__nv_bfloat162*)(Chi + (size_t)row * N + c) = __halves2bfloat162(h0, h1);
                    *(__nv_bfloat162*)(Clo + (size_t)row * N + c) =
                        __floats2bfloat162_rn(v0 - __bfloat162float(h0),
                                              v1 - __bfloat162float(h1));
                } else {
                    *(float2*)(Cf + (size_t)row * N + c) = make_float2(v0, v1);
                }
            }
        }
    }
}

// ---------------- LayerNorm -> bf16 hi/lo ----------------
__global__ void __launch_bounds__(256) ln_hilo(const float* __restrict__ x,
                                               const float* __restrict__ g,
                                               const float* __restrict__ b,
                                               __nv_bfloat16* __restrict__ oh,
                                               __nv_bfloat16* __restrict__ ol)
{
    size_t row = blockIdx.x;
    int t = threadIdx.x;
    float4 xv = ((const float4*)(x + row * ND))[t];
    float s  = xv.x + xv.y + xv.z + xv.w;
    float ss = xv.x*xv.x + xv.y*xv.y + xv.z*xv.z + xv.w*xv.w;
#pragma unroll
    for (int o = 16; o; o >>= 1) {
        s  += __shfl_xor_sync(0xffffffffu, s,  o);
        ss += __shfl_xor_sync(0xffffffffu, ss, o);
    }
    __shared__ float sh_s[8], sh_ss[8];
    if ((t & 31) == 0) { sh_s[t >> 5] = s; sh_ss[t >> 5] = ss; }
    __syncthreads();
    float ts = 0.f, tss = 0.f;
#pragma unroll
    for (int i = 0; i < 8; i++) { ts += sh_s[i]; tss += sh_ss[i]; }
    float mean = ts * (1.f / ND);
    float var  = tss * (1.f / ND) - mean * mean;
    float rstd = rsqrtf(var + 1e-5f);
    float4 gv = ((const float4*)g)[t];
    float4 bv = ((const float4*)b)[t];
    float o0 = (xv.x - mean) * rstd * gv.x + bv.x;
    float o1 = (xv.y - mean) * rstd * gv.y + bv.y;
    float o2 = (xv.z - mean) * rstd * gv.z + bv.z;
    float o3 = (xv.w - mean) * rstd * gv.w + bv.w;
    __nv_bfloat16 h0 = __float2bfloat16(o0), h1 = __float2bfloat16(o1);
    __nv_bfloat16 h2 = __float2bfloat16(o2), h3 = __float2bfloat16(o3);
    __nv_bfloat162* ph = (__nv_bfloat162*)(oh + row * ND);
    __nv_bfloat162* pl = (__nv_bfloat162*)(ol + row * ND);
    ph[2*t]   = __halves2bfloat162(h0, h1);
    ph[2*t+1] = __halves2bfloat162(h2, h3);
    pl[2*t]   = __floats2bfloat162_rn(o0 - __bfloat162float(h0), o1 - __bfloat162float(h1));
    pl[2*t+1] = __floats2bfloat162_rn(o2 - __bfloat162float(h2), o3 - __bfloat162float(h3));
}

// ---------------- softmax (in-place fp32) + bf16 hi/lo ----------------
__global__ void __launch_bounds__(256) softmax_hilo(float* __restrict__ w,
                                                    __nv_bfloat16* __restrict__ oh,
                                                    __nv_bfloat16* __restrict__ ol)
{
    float* p = w + (size_t)blockIdx.x * NS;
    int t = threadIdx.x;
    float4 v0 = ((const float4*)p)[t];
    float4 v1 = ((const float4*)p)[t + 256];
    float mx = fmaxf(fmaxf(fmaxf(v0.x, v0.y), fmaxf(v0.z, v0.w)),
                     fmaxf(fmaxf(v1.x, v1.y), fmaxf(v1.z, v1.w)));
#pragma unroll
    for (int o = 16; o; o >>= 1) mx = fmaxf(mx, __shfl_xor_sync(0xffffffffu, mx, o));
    __shared__ float shm[8], shs[8];
    if ((t & 31) == 0) shm[t >> 5] = mx;
    __syncthreads();
    mx = shm[0];
#pragma unroll
    for (int i = 1; i < 8; i++) mx = fmaxf(mx, shm[i]);
    float e[8];
    e[0] = __expf(v0.x - mx); e[1] = __expf(v0.y - mx);
    e[2] = __expf(v0.z - mx); e[3] = __expf(v0.w - mx);
    e[4] = __expf(v1.x - mx); e[5] = __expf(v1.y - mx);
    e[6] = __expf(v1.z - mx); e[7] = __expf(v1.w - mx);
    float s = e[0]+e[1]+e[2]+e[3]+e[4]+e[5]+e[6]+e[7];
#pragma unroll
    for (int o = 16; o; o >>= 1) s += __shfl_xor_sync(0xffffffffu, s, o);
    if ((t & 31) == 0) shs[t >> 5] = s;
    __syncthreads();
    s = 0.f;
#pragma unroll
    for (int i = 0; i < 8; i++) s += shs[i];
    float inv = 1.f / s;
#pragma unroll
    for (int i = 0; i < 8; i++) e[i] *= inv;
    ((float4*)p)[t]       = make_float4(e[0], e[1], e[2], e[3]);
    ((float4*)p)[t + 256] = make_float4(e[4], e[5], e[6], e[7]);

    __nv_bfloat162* ph = (__nv_bfloat162*)(oh + (size_t)blockIdx.x * NS);
    __nv_bfloat162* pl = (__nv_bfloat162*)(ol + (size_t)blockIdx.x * NS);
#pragma unroll
    for (int q = 0; q < 2; q++) {
        int base = q ? 512 : 0;
        int ei = q * 4;
        __nv_bfloat16 h0 = __float2bfloat16(e[ei+0]);
        __nv_bfloat16 h1 = __float2bfloat16(e[ei+1]);
        __nv_bfloat16 h2 = __float2bfloat16(e[ei+2]);
        __nv_bfloat16 h3 = __float2bfloat16(e[ei+3]);
        ph[base + 2*t]   = __halves2bfloat162(h0, h1);
        ph[base + 2*t+1] = __halves2bfloat162(h2, h3);
        pl[base + 2*t]   = __floats2bfloat162_rn(e[ei+0] - __bfloat162float(h0),
                                                 e[ei+1] - __bfloat162float(h1));
        pl[base + 2*t+1] = __floats2bfloat162_rn(e[ei+2] - __bfloat162float(h2),
                                                 e[ei+3] - __bfloat162float(h3));
    }
}

// ---------------- weight transpose + split ----------------
__global__ void __launch_bounds__(256) wt_conv(const float* __restrict__ W,
                                               __nv_bfloat16* __restrict__ Th,
                                               __nv_bfloat16* __restrict__ Tl)
{
    __shared__ float tile[64][65];
    int k0 = blockIdx.y * 64, n0 = blockIdx.x * 64;
#pragma unroll
    for (int u = threadIdx.x; u < 4096; u += 256) {
        int r = u >> 6, c = u & 63;
        tile[r][c] = W[(size_t)(k0 + r) * ND + n0 + c];
    }
    __syncthreads();
#pragma unroll
    for (int u = threadIdx.x; u < 4096; u += 256) {
        int r = u >> 6, c = u & 63;
        float v = tile[c][r];
        __nv_bfloat16 h = __float2bfloat16(v);
        Th[(size_t)(n0 + r) * ND + k0 + c] = h;
        Tl[(size_t)(n0 + r) * ND + k0 + c] = __float2bfloat16(v - __bfloat162float(h));
    }
}

// ---------------- bf16 transpose (k -> kT per batch) ----------------
__global__ void __launch_bounds__(256) kt_kernel(const __nv_bfloat16* __restrict__ ih,
                                                 const __nv_bfloat16* __restrict__ il,
                                                 __nv_bfloat16* __restrict__ oh,
                                                 __nv_bfloat16* __restrict__ ol)
{
    __shared__ __nv_bfloat16 th[64][65], tl[64][65];
    int b = blockIdx.z;
    int d0 = blockIdx.x * 64, s0 = blockIdx.y * 64;
    const size_t ib = (size_t)b * NS * ND;
    const size_t ob = (size_t)b * ND * NS;
#pragma unroll
    for (int u = threadIdx.x; u < 4096; u += 256) {
        int r = u >> 6, c = u & 63;
        th[r][c] = ih[ib + (size_t)(s0 + r) * ND + d0 + c];
        tl[r][c] = il[ib + (size_t)(s0 + r) * ND + d0 + c];
    }
    __syncthreads();
#pragma unroll
    for (int u = threadIdx.x; u < 4096; u += 256) {
        int r = u >> 6, c = u & 63;
        oh[ob + (size_t)(d0 + r) * NS + s0 + c] = th[c][r];
        ol[ob + (size_t)(d0 + r) * NS + s0 + c] = tl[c][r];
    }
}

// ---------------- driver ----------------
extern "C" void kernel_launch(void* const* d_in, const int* in_sizes, int n_in,
                              void* d_out, int out_size)
{
    const float* x    = (const float*)d_in[0];
    const int*   mask = (const int*)  d_in[1];
    const float* ln1g = (const float*)d_in[2];
    const float* ln1b = (const float*)d_in[3];
    const float* Wq   = (const float*)d_in[4];
    const float* bq   = (const float*)d_in[5];
    const float* Wk   = (const float*)d_in[6];
    const float* bk   = (const float*)d_in[7];
    const float* Wo   = (const float*)d_in[8];
    const float* bo   = (const float*)d_in[9];
    const float* ln2g = (const float*)d_in[10];
    const float* ln2b = (const float*)d_in[11];
    const float* W1   = (const float*)d_in[12];
    const float* b1   = (const float*)d_in[13];
    const float* W2   = (const float*)d_in[14];
    const float* b2   = (const float*)d_in[15];

    float* out  = (float*)d_out;
    float* wout = out + (size_t)NROWS * ND;

    __nv_bfloat16 *xn_h, *xn_l, *q_h, *q_l, *k_h, *k_l, *kT_h, *kT_l;
    __nv_bfloat16 *w_h, *w_l, *at_h, *at_l, *xn2_h, *xn2_l, *h_h, *h_l, *wt;
    float* x2;
    cudaGetSymbolAddress((void**)&xn_h, g_xn_h);   cudaGetSymbolAddress((void**)&xn_l, g_xn_l);
    cudaGetSymbolAddress((void**)&q_h,  g_q_h);    cudaGetSymbolAddress((void**)&q_l,  g_q_l);
    cudaGetSymbolAddress((void**)&k_h,  g_k_h);    cudaGetSymbolAddress((void**)&k_l,  g_k_l);
    cudaGetSymbolAddress((void**)&kT_h, g_kT_h);   cudaGetSymbolAddress((void**)&kT_l, g_kT_l);
    cudaGetSymbolAddress((void**)&w_h,  g_w_h);    cudaGetSymbolAddress((void**)&w_l,  g_w_l);
    cudaGetSymbolAddress((void**)&at_h, g_at_h);   cudaGetSymbolAddress((void**)&at_l, g_at_l);
    cudaGetSymbolAddress((void**)&xn2_h,g_xn2_h);  cudaGetSymbolAddress((void**)&xn2_l,g_xn2_l);
    cudaGetSymbolAddress((void**)&h_h,  g_h_h);    cudaGetSymbolAddress((void**)&h_l,  g_h_l);
    cudaGetSymbolAddress((void**)&x2,   g_x2);
    cudaGetSymbolAddress((void**)&wt,   g_wt);

    __nv_bfloat16 *wq_h = wt + 0*2*WSZ, *wq_l = wt + 0*2*WSZ + WSZ;
    __nv_bfloat16 *wk_h = wt + 1*2*WSZ, *wk_l = wt + 1*2*WSZ + WSZ;
    __nv_bfloat16 *wo_h = wt + 2*2*WSZ, *wo_l = wt + 2*2*WSZ + WSZ;
    __nv_bfloat16 *w1_h = wt + 3*2*WSZ, *w1_l = wt + 3*2*WSZ + WSZ;
    __nv_bfloat16 *w2_h = wt + 4*2*WSZ, *w2_l = wt + 4*2*WSZ + WSZ;

    cudaFuncSetAttribute(gemm_tc<true,false,false,false,true>,
                         cudaFuncAttributeMaxDynamicSharedMemorySize, SMEMSZ);
    cudaFuncSetAttribute(gemm_tc<false,false,true,false,false>,
                         cudaFuncAttributeMaxDynamicSharedMemorySize, SMEMSZ);
    cudaFuncSetAttribute(gemm_tc<false,false,false,false,true>,
                         cudaFuncAttributeMaxDynamicSharedMemorySize, SMEMSZ);
    cudaFuncSetAttribute(gemm_tc<true,false,false,true,false>,
                         cudaFuncAttributeMaxDynamicSharedMemorySize, SMEMSZ);
    cudaFuncSetAttribute(gemm_tc<true,true,false,false,true>,
                         cudaFuncAttributeMaxDynamicSharedMemorySize, SMEMSZ);

    dim3 gW(16, 16);
    wt_conv<<<gW, 256>>>(Wq, wq_h, wq_l);
    wt_conv<<<gW, 256>>>(Wk, wk_h, wk_l);
    wt_conv<<<gW, 256>>>(Wo, wo_h, wo_l);
    wt_conv<<<gW, 256>>>(W1, w1_h, w1_l);
    wt_conv<<<gW, 256>>>(W2, w2_h, w2_l);

    // 1) xn = LN1(x)
    ln_hilo<<<NROWS, 256>>>(x, ln1g, ln1b, xn_h, xn_l);

    dim3 gP(ND / 128, NROWS / 128, 1);
    // 2) q, k projections (v == k, faithful reference bug)
    gemm_tc<true,false,false,false,true><<<gP, 256, SMEMSZ>>>(
        xn_h, xn_l, wq_h, wq_l, NROWS, ND, ND, 0, 0, 0,
        nullptr, q_h, q_l, bq, nullptr, nullptr, 1.f);
    gemm_tc<true,false,false,false,true><<<gP, 256, SMEMSZ>>>(
        xn_h, xn_l, wk_h, wk_l, NROWS, ND, ND, 0, 0, 0,
        nullptr, k_h, k_l, bk, nullptr, nullptr, 1.f);

    // 3) kT for attn@v
    kt_kernel<<<dim3(ND / 64, NS / 64, NB), 256>>>(k_h, k_l, kT_h, kT_l);

    // 4) scores = (q @ k^T)/32, masked -> wout (fp32)
    dim3 gS(NS / 128, NS / 128, NB);
    gemm_tc<false,false,true,false,false><<<gS, 256, SMEMSZ>>>(
        q_h, q_l, k_h, k_l, NS, NS, ND,
        (long long)NS * ND, (long long)NS * ND, (long long)NS * NS,
        wout, nullptr, nullptr, nullptr, nullptr, mask, 0.03125f);

    // 5) softmax in place + hi/lo
    softmax_hilo<<<NROWS, 256>>>(wout, w_h, w_l);

    // 6) attn = w @ v  (v == k)
    dim3 gA(ND / 128, NS / 128, NB);
    gemm_tc<false,false,false,false,true><<<gA, 256, SMEMSZ>>>(
        w_h, w_l, kT_h, kT_l, NS, ND, NS,
        (long long)NS * NS, (long long)ND * NS, (long long)NS * ND,
        nullptr, at_h, at_l, nullptr, nullptr, nullptr, 1.f);

    // 7) x2 = x + attn @ Wo + bo
    gemm_tc<true,false,false,true,false><<<gP, 256, SMEMSZ>>>(
        at_h, at_l, wo_h, wo_l, NROWS, ND, ND, 0, 0, 0,
        x2, nullptr, nullptr, bo, x, nullptr, 1.f);

    // 8) xn2 = LN2(x2)
    ln_hilo<<<NROWS, 256>>>(x2, ln2g, ln2b, xn2_h, xn2_l);

    // 9) h = relu(xn2 @ W1 + b1)
    gemm_tc<true,true,false,false,true><<<gP, 256, SMEMSZ>>>(
        xn2_h, xn2_l, w1_h, w1_l, NROWS, ND, ND, 0, 0, 0,
        nullptr, h_h, h_l, b1, nullptr, nullptr, 1.f);

    // 10) out = x2 + h @ W2 + b2
    gemm_tc<true,false,false,true,false><<<gP, 256, SMEMSZ>>>(
        h_h, h_l, w2_h, w2_l, NROWS, ND, ND, 0, 0, 0,
        out, nullptr, nullptr, b2, x2, nullptr, 1.f);
}